// round 5
// baseline (speedup 1.0000x reference)
#include <cuda_runtime.h>

#define TH 16
#define TW 64
#define NT 384
#define HIMG 512
#define WIMG 512
#define SAW 68   // padded row stride for s_a (272B, 16B-multiple)
#define SCW 36   // padded row stride for s_c (144B, 16B-multiple)

typedef unsigned long long u64;

__device__ __forceinline__ u64 pk2(float lo, float hi) {
    u64 r; asm("mov.b64 %0, {%1, %2};" : "=l"(r) : "f"(lo), "f"(hi)); return r;
}
__device__ __forceinline__ void upk2(u64 v, float& lo, float& hi) {
    asm("mov.b64 {%0, %1}, %2;" : "=f"(lo), "=f"(hi) : "l"(v));
}
__device__ __forceinline__ u64 fma2_(u64 a, u64 b, u64 c) {
    u64 d; asm("fma.rn.f32x2 %0, %1, %2, %3;" : "=l"(d) : "l"(a), "l"(b), "l"(c)); return d;
}
__device__ __forceinline__ u64 mul2_(u64 a, u64 b) {
    u64 d; asm("mul.rn.f32x2 %0, %1, %2;" : "=l"(d) : "l"(a), "l"(b)); return d;
}
__device__ __forceinline__ u64 add2_(u64 a, u64 b) {
    u64 d; asm("add.rn.f32x2 %0, %1, %2;" : "=l"(d) : "l"(a), "l"(b)); return d;
}

__global__ __launch_bounds__(NT, 3) void jpeg_kernel(
    const float* __restrict__ in, const float* __restrict__ quant,
    const float* __restrict__ dct, float* __restrict__ out)
{
    __shared__ __align__(16) float s_a[3][TH][SAW];   // y full-res; V scratch; recon
    __shared__ __align__(16) float s_c[2][TH/2][SCW]; // half-res chroma
    __shared__ __align__(16) float s_d[8][8];         // D (dense)
    __shared__ __align__(16) float s_dt[8][8];        // D^T (dense)
    __shared__ __align__(16) u64   s_d2[8][8];        // (D[i][j], D[i][j]) dup pairs
    __shared__ __align__(16) u64   s_e2[8][4];        // (E[i][h], E[i][h]) dup pairs
    __shared__ __align__(16) u64   s_et2[4][4];       // (E[2l][h], E[2l+1][h])
    __shared__ __align__(16) float s_q[3][8][8];      // quant
    __shared__ __align__(16) float s_rq[3][8][8];     // 1/q

    const int tid = threadIdx.x;
    const int b   = blockIdx.z;
    const int ty0 = blockIdx.y * TH;
    const int tx0 = blockIdx.x * TW;

    // ---- tables ----
    if (tid < 64) {
        float v = dct[tid];
        int i = tid >> 3, j = tid & 7;
        s_d[i][j]  = v;
        s_dt[j][i] = v;
        s_d2[i][j] = pk2(v, v);
    } else if (tid < 256) {
        int i = tid - 64;
        float qv = rintf(quant[i] * 255.0f);
        float q1 = rintf((qv * 50.0f + 50.0f) / 100.0f);
        float q  = fminf(fmaxf(q1, 1.0f), 255.0f);
        int ci = i >> 6, ri = (i >> 3) & 7, li = i & 7;
        s_q[ci][ri][li]  = q;
        s_rq[ci][ri][li] = 1.0f / q;
    } else if (tid < 288) {
        int t = tid - 256;
        int i = t >> 2, h = t & 3;
        float e = dct[i * 8 + 2 * h] + dct[i * 8 + 2 * h + 1];
        s_e2[i][h] = pk2(e, e);
    } else if (tid < 304) {
        int t = tid - 288;
        int h = t >> 2, lp = t & 3;
        float e0 = dct[(2*lp)   * 8 + 2*h] + dct[(2*lp)   * 8 + 2*h + 1];
        float e1 = dct[(2*lp+1) * 8 + 2*h] + dct[(2*lp+1) * 8 + 2*h + 1];
        s_et2[h][lp] = pk2(e0, e1);
    }

    const size_t plane = (size_t)HIMG * WIMG;
    const float* base  = in  + (size_t)b * 3 * plane;
    float*       obase = out + (size_t)b * 3 * plane;

    // ---- phase 1: RGB->YCbCr + clip; y full-res, chroma 2x2-mean half-res ----
    if (tid < (TH/2) * (TW/2)) {                 // 256 quads
        const int qy = tid >> 5;
        const int qx = tid & 31;
        const int py = qy * 2, px = qx * 2;
        const size_t idx = (size_t)(ty0 + py) * WIMG + (tx0 + px);

        const u64 C255 = pk2(255.0f, 255.0f);
        const u64 CY0 = pk2(0.299f,0.299f), CY1 = pk2(0.587f,0.587f), CY2 = pk2(0.114f,0.114f);
        const u64 CB0 = pk2(-0.168735892f,-0.168735892f), CB1 = pk2(-0.331264108f,-0.331264108f), CB2 = pk2(0.5f,0.5f);
        const u64 CR0 = pk2(0.5f,0.5f), CR1 = pk2(-0.418687589f,-0.418687589f), CR2 = pk2(-0.081312411f,-0.081312411f);
        const u64 C128 = pk2(128.0f, 128.0f);

        u64 r0 = mul2_(C255, *(const u64*)&base[idx]);
        u64 r1 = mul2_(C255, *(const u64*)&base[idx + WIMG]);
        u64 g0 = mul2_(C255, *(const u64*)&base[plane + idx]);
        u64 g1 = mul2_(C255, *(const u64*)&base[plane + idx + WIMG]);
        u64 b0 = mul2_(C255, *(const u64*)&base[2*plane + idx]);
        u64 b1 = mul2_(C255, *(const u64*)&base[2*plane + idx + WIMG]);

        u64 y0  = fma2_(CY2, b0, fma2_(CY1, g0, mul2_(CY0, r0)));
        u64 y1  = fma2_(CY2, b1, fma2_(CY1, g1, mul2_(CY0, r1)));
        u64 cb0 = add2_(C128, fma2_(CB2, b0, fma2_(CB1, g0, mul2_(CB0, r0))));
        u64 cb1 = add2_(C128, fma2_(CB2, b1, fma2_(CB1, g1, mul2_(CB0, r1))));
        u64 cr0 = add2_(C128, fma2_(CR2, b0, fma2_(CR1, g0, mul2_(CR0, r0))));
        u64 cr1 = add2_(C128, fma2_(CR2, b1, fma2_(CR1, g1, mul2_(CR0, r1))));

        #define CL(v) fminf(fmaxf((v), 0.0f), 255.0f)
        float y00,y01,y10,y11;  upk2(y0,y00,y01);  upk2(y1,y10,y11);
        y00 = CL(y00)-128.0f; y01 = CL(y01)-128.0f;
        y10 = CL(y10)-128.0f; y11 = CL(y11)-128.0f;
        *(u64*)&s_a[0][py][px]   = pk2(y00, y01);
        *(u64*)&s_a[0][py+1][px] = pk2(y10, y11);

        float cb00,cb01,cb10,cb11;  upk2(cb0,cb00,cb01);  upk2(cb1,cb10,cb11);
        float cr00,cr01,cr10,cr11;  upk2(cr0,cr00,cr01);  upk2(cr1,cr10,cr11);
        float cbm = 0.25f * (((CL(cb00)+CL(cb01))+CL(cb10))+CL(cb11)) - 128.0f;
        float crm = 0.25f * (((CL(cr00)+CL(cr01))+CL(cr10))+CL(cr11)) - 128.0f;
        s_c[0][qy][qx] = cbm;
        s_c[1][qy][qx] = crm;
    }
    __syncthreads();

    // ---- assignment: 48 (channel, block) units * 8 row-threads ----
    const int blk = tid >> 3;
    const int r   = tid & 7;
    int c, by, bx;
    if (blk < 16) { c = 0; by = blk >> 3; bx = blk & 7; }
    else { int t = blk - 16; c = 1 + (t >> 4); int rem = t & 15; by = rem >> 3; bx = rem & 7; }

    // ---- DCT -> quant/dequant -> V = dec*D (row-local, packed f32x2) ----
    u64 V01, V23, V45, V67;
    {
        u64 a01 = 0, a23 = 0, a45 = 0, a67 = 0;  // acc pairs
        if (c == 0) {
            u64 t01 = 0, t23 = 0, t45 = 0, t67 = 0;
            const char* pX = (const char*)&s_a[0][by*8][bx*8];
            #pragma unroll
            for (int j = 0; j < 8; j++) {
                u64 dd = s_d2[r][j];
                ulonglong2 x0 = *(const ulonglong2*)(pX + j*(SAW*4));
                ulonglong2 x1 = *(const ulonglong2*)(pX + j*(SAW*4) + 16);
                t01 = fma2_(dd, x0.x, t01);  t23 = fma2_(dd, x0.y, t23);
                t45 = fma2_(dd, x1.x, t45);  t67 = fma2_(dd, x1.y, t67);
            }
            float t[8];
            upk2(t01, t[0], t[1]);  upk2(t23, t[2], t[3]);
            upk2(t45, t[4], t[5]);  upk2(t67, t[6], t[7]);
            #pragma unroll
            for (int k = 0; k < 8; k++) {
                u64 tk = pk2(t[k], t[k]);
                ulonglong2 m0 = *(const ulonglong2*)&s_dt[k][0];
                ulonglong2 m1 = *(const ulonglong2*)&s_dt[k][4];
                a01 = fma2_(tk, m0.x, a01);  a23 = fma2_(tk, m0.y, a23);
                a45 = fma2_(tk, m1.x, a45);  a67 = fma2_(tk, m1.y, a67);
            }
        } else {
            const int cc = c - 1;
            u64 p01 = 0, p23 = 0;
            const char* pC = (const char*)&s_c[cc][by*4][bx*4];
            #pragma unroll
            for (int jh = 0; jh < 4; jh++) {
                u64 ee = s_e2[r][jh];
                ulonglong2 xh = *(const ulonglong2*)(pC + jh*(SCW*4));
                p01 = fma2_(ee, xh.x, p01);  p23 = fma2_(ee, xh.y, p23);
            }
            float p[4];
            upk2(p01, p[0], p[1]);  upk2(p23, p[2], p[3]);
            #pragma unroll
            for (int h = 0; h < 4; h++) {
                u64 ph = pk2(p[h], p[h]);
                ulonglong2 e0 = *(const ulonglong2*)&s_et2[h][0];
                ulonglong2 e1 = *(const ulonglong2*)&s_et2[h][2];
                a01 = fma2_(ph, e0.x, a01);  a23 = fma2_(ph, e0.y, a23);
                a45 = fma2_(ph, e1.x, a45);  a67 = fma2_(ph, e1.y, a67);
            }
        }
        // quantize / dequantize (scalar rints; unpack is register-free)
        float a[8];
        upk2(a01, a[0], a[1]);  upk2(a23, a[2], a[3]);
        upk2(a45, a[4], a[5]);  upk2(a67, a[6], a[7]);
        const float4 q0  = *(const float4*)&s_q[c][r][0];
        const float4 q1  = *(const float4*)&s_q[c][r][4];
        const float4 rq0 = *(const float4*)&s_rq[c][r][0];
        const float4 rq1 = *(const float4*)&s_rq[c][r][4];
        float dec[8];
        dec[0] = rintf(rintf(a[0]*rq0.x)*q0.x);  dec[1] = rintf(rintf(a[1]*rq0.y)*q0.y);
        dec[2] = rintf(rintf(a[2]*rq0.z)*q0.z);  dec[3] = rintf(rintf(a[3]*rq0.w)*q0.w);
        dec[4] = rintf(rintf(a[4]*rq1.x)*q1.x);  dec[5] = rintf(rintf(a[5]*rq1.y)*q1.y);
        dec[6] = rintf(rintf(a[6]*rq1.z)*q1.z);  dec[7] = rintf(rintf(a[7]*rq1.w)*q1.w);
        // V = dec * D
        V01 = 0; V23 = 0; V45 = 0; V67 = 0;
        #pragma unroll
        for (int k = 0; k < 8; k++) {
            u64 dk = pk2(dec[k], dec[k]);
            ulonglong2 m0 = *(const ulonglong2*)&s_d[k][0];
            ulonglong2 m1 = *(const ulonglong2*)&s_d[k][4];
            V01 = fma2_(dk, m0.x, V01);  V23 = fma2_(dk, m0.y, V23);
            V45 = fma2_(dk, m1.x, V45);  V67 = fma2_(dk, m1.y, V67);
        }
    }
    __syncthreads();  // all X reads done -> safe to overwrite s_a
    char* pW = (char*)&s_a[c][by*8][bx*8];
    {
        ulonglong2 w0; w0.x = V01; w0.y = V23;
        ulonglong2 w1; w1.x = V45; w1.y = V67;
        *(ulonglong2*)(pW + r*(SAW*4))      = w0;
        *(ulonglong2*)(pW + r*(SAW*4) + 16) = w1;
    }
    __syncthreads();

    // ---- IDCT stage 2: Z = D^T * V (packed) ----
    {
        u64 z01 = 0, z23 = 0, z45 = 0, z67 = 0;
        #pragma unroll
        for (int j = 0; j < 8; j++) {
            u64 dd = s_d2[j][r];
            ulonglong2 v0 = *(const ulonglong2*)(pW + j*(SAW*4));
            ulonglong2 v1 = *(const ulonglong2*)(pW + j*(SAW*4) + 16);
            z01 = fma2_(dd, v0.x, z01);  z23 = fma2_(dd, v0.y, z23);
            z45 = fma2_(dd, v1.x, z45);  z67 = fma2_(dd, v1.y, z67);
        }
        const u64 offp = (c == 0) ? pk2(128.0f, 128.0f) : 0ULL;
        z01 = add2_(z01, offp);  z23 = add2_(z23, offp);
        z45 = add2_(z45, offp);  z67 = add2_(z67, offp);
        __syncthreads();  // all V reads done -> safe to overwrite
        ulonglong2 w0; w0.x = z01; w0.y = z23;
        ulonglong2 w1; w1.x = z45; w1.y = z67;
        *(ulonglong2*)(pW + r*(SAW*4))      = w0;
        *(ulonglong2*)(pW + r*(SAW*4) + 16) = w1;
    }
    __syncthreads();

    // ---- phase 5: YCbCr -> RGB, clip, round, store ----
    if (tid < (TH * TW) / 4) {
        const int py  = tid >> 4;
        const int px4 = (tid & 15) * 4;
        ulonglong2 yv  = *(const ulonglong2*)&s_a[0][py][px4];
        ulonglong2 cbv = *(const ulonglong2*)&s_a[1][py][px4];
        ulonglong2 crv = *(const ulonglong2*)&s_a[2][py][px4];

        const u64 C1402 = pk2(1.402f, 1.402f);
        const u64 CM344 = pk2(-0.344136286f, -0.344136286f);
        const u64 CM714 = pk2(-0.714136286f, -0.714136286f);
        const u64 C1772 = pk2(1.772f, 1.772f);

        u64 R01 = fma2_(C1402, crv.x, yv.x);
        u64 R23 = fma2_(C1402, crv.y, yv.y);
        u64 G01 = fma2_(CM714, crv.x, fma2_(CM344, cbv.x, yv.x));
        u64 G23 = fma2_(CM714, crv.y, fma2_(CM344, cbv.y, yv.y));
        u64 B01 = fma2_(C1772, cbv.x, yv.x);
        u64 B23 = fma2_(C1772, cbv.y, yv.y);

        #define FIN(v) (rintf(fminf(fmaxf((v), 0.0f), 255.0f)) * (1.0f/255.0f))
        float4 R, G, Bv;
        upk2(R01, R.x, R.y);   upk2(R23, R.z, R.w);
        upk2(G01, G.x, G.y);   upk2(G23, G.z, G.w);
        upk2(B01, Bv.x, Bv.y); upk2(B23, Bv.z, Bv.w);
        R.x = FIN(R.x);  R.y = FIN(R.y);  R.z = FIN(R.z);  R.w = FIN(R.w);
        G.x = FIN(G.x);  G.y = FIN(G.y);  G.z = FIN(G.z);  G.w = FIN(G.w);
        Bv.x = FIN(Bv.x); Bv.y = FIN(Bv.y); Bv.z = FIN(Bv.z); Bv.w = FIN(Bv.w);

        const size_t idx = (size_t)(ty0 + py) * WIMG + (tx0 + px4);
        *(float4*)&obase[idx]           = R;
        *(float4*)&obase[plane + idx]   = G;
        *(float4*)&obase[2*plane + idx] = Bv;
    }
}

extern "C" void kernel_launch(void* const* d_in, const int* in_sizes, int n_in,
                              void* d_out, int out_size)
{
    const float* x = nullptr;
    const float* q = nullptr;
    const float* d = nullptr;
    int nimg = 0;
    for (int i = 0; i < n_in; i++) {
        if (in_sizes[i] == 192)      q = (const float*)d_in[i];
        else if (in_sizes[i] == 64)  d = (const float*)d_in[i];
        else { x = (const float*)d_in[i]; nimg = in_sizes[i] / (3 * HIMG * WIMG); }
    }
    dim3 grid(WIMG / TW, HIMG / TH, nimg);
    jpeg_kernel<<<grid, NT>>>(x, q, d, (float*)d_out);
}

// round 6
// speedup vs baseline: 1.3039x; 1.3039x over previous
#include <cuda_runtime.h>

#define TH 16
#define TW 64
#define NT 256
#define HIMG 512
#define WIMG 512
#define SAW 68   // padded row stride for s_a
#define SCW 36   // padded row stride for s_c (half-res chroma)

__constant__ float c_D[64];   // DCT matrix, row-major

__global__ __launch_bounds__(NT, 5) void jpeg_kernel(
    const float* __restrict__ in, const float* __restrict__ quant,
    const float* __restrict__ dct, float* __restrict__ out)
{
    __shared__ __align__(16) float s_a[3][TH][SAW];   // y / A' / V / Z
    __shared__ __align__(16) float s_c[2][TH/2][SCW]; // half-res chroma
    __shared__ __align__(16) float s_d[8][8];         // D (lane-varying reads)
    __shared__ __align__(16) float s_dt[8][8];        // D^T (lane-varying reads)
    __shared__ __align__(16) float s_e[8][4];         // E (lane-varying reads)
    __shared__ __align__(16) float s_q[3][8][8];
    __shared__ __align__(16) float s_rq[3][8][8];

    const int tid = threadIdx.x;
    const int b   = blockIdx.z;
    const int ty0 = blockIdx.y * TH;
    const int tx0 = blockIdx.x * TW;

    // ---- tables ----
    if (tid < 64) {
        float v = dct[tid];
        int i = tid >> 3, j = tid & 7;
        s_d[i][j]  = v;
        s_dt[j][i] = v;
    }
    if (tid < 32) {
        int i = tid >> 2, h = tid & 3;
        s_e[i][h] = dct[i * 8 + 2 * h] + dct[i * 8 + 2 * h + 1];
    }
    if (tid >= 64) {
        int i = tid - 64;
        float qv = rintf(quant[i] * 255.0f);
        float q1 = rintf((qv * 50.0f + 50.0f) / 100.0f);
        float q  = fminf(fmaxf(q1, 1.0f), 255.0f);
        int ci = i >> 6, ri = (i >> 3) & 7, li = i & 7;
        s_q[ci][ri][li]  = q;
        s_rq[ci][ri][li] = 1.0f / q;
    }

    const size_t plane = (size_t)HIMG * WIMG;
    const float* base  = in  + (size_t)b * 3 * plane;
    float*       obase = out + (size_t)b * 3 * plane;

    // ---- phase 1: RGB->YCbCr + clip; y full-res, chroma 2x2-mean half-res ----
    {
        const int qy = tid >> 5;                 // 0..7
        const int qx = tid & 31;                 // 0..31
        const int py = qy * 2, px = qx * 2;
        const size_t idx = (size_t)(ty0 + py) * WIMG + (tx0 + px);

        float2 r0 = *(const float2*)&base[idx];
        float2 r1 = *(const float2*)&base[idx + WIMG];
        float2 g0 = *(const float2*)&base[plane + idx];
        float2 g1 = *(const float2*)&base[plane + idx + WIMG];
        float2 b0 = *(const float2*)&base[2*plane + idx];
        float2 b1 = *(const float2*)&base[2*plane + idx + WIMG];

        float r00 = 255.0f*r0.x, r01 = 255.0f*r0.y, r10 = 255.0f*r1.x, r11 = 255.0f*r1.y;
        float g00 = 255.0f*g0.x, g01 = 255.0f*g0.y, g10 = 255.0f*g1.x, g11 = 255.0f*g1.y;
        float b00 = 255.0f*b0.x, b01 = 255.0f*b0.y, b10 = 255.0f*b1.x, b11 = 255.0f*b1.y;

        #define YV(R,G,B)  fmaf(0.114f,(B), fmaf(0.587f,(G), 0.299f*(R)))
        #define CBV(R,G,B) (fmaf(0.5f,(B),  fmaf(-0.331264108f,(G), -0.168735892f*(R))) + 128.0f)
        #define CRV(R,G,B) (fmaf(-0.081312411f,(B), fmaf(-0.418687589f,(G), 0.5f*(R))) + 128.0f)
        #define CL(v) fminf(fmaxf((v), 0.0f), 255.0f)

        float y00 = CL(YV(r00,g00,b00)) - 128.0f;
        float y01 = CL(YV(r01,g01,b01)) - 128.0f;
        float y10 = CL(YV(r10,g10,b10)) - 128.0f;
        float y11 = CL(YV(r11,g11,b11)) - 128.0f;

        float cb00 = CL(CBV(r00,g00,b00)), cb01 = CL(CBV(r01,g01,b01));
        float cb10 = CL(CBV(r10,g10,b10)), cb11 = CL(CBV(r11,g11,b11));
        float cr00 = CL(CRV(r00,g00,b00)), cr01 = CL(CRV(r01,g01,b01));
        float cr10 = CL(CRV(r10,g10,b10)), cr11 = CL(CRV(r11,g11,b11));

        float cbm = 0.25f * (((cb00 + cb01) + cb10) + cb11) - 128.0f;
        float crm = 0.25f * (((cr00 + cr01) + cr10) + cr11) - 128.0f;

        *(float2*)&s_a[0][py][px]   = make_float2(y00, y01);
        *(float2*)&s_a[0][py+1][px] = make_float2(y10, y11);
        s_c[0][qy][qx] = cbm;
        s_c[1][qy][qx] = crm;
    }
    __syncthreads();

    // ---- assignment: 48 units * 4 threads (rows r and r+4) ----
    const bool act = tid < 192;
    const int unit = tid >> 2;    // 0..47
    const int r    = tid & 3;
    int c, by, bx;
    if (unit < 16) { c = 0; by = unit >> 3; bx = unit & 7; }
    else { int t = unit - 16; c = 1 + (t >> 4); int rem = t & 15; by = rem >> 3; bx = rem & 7; }
    const int ra = r, rb = r + 4;
    float* pW = &s_a[c][by*8][bx*8];

    // ---- stage 1: A' = X * D^T (row-local; uniform const coeffs) ----
    if (act) {
        if (c == 0) {
            #pragma unroll
            for (int pass = 0; pass < 2; pass++) {
                const int rr = pass ? rb : ra;
                const float4 x0 = *(const float4*)(pW + rr*SAW);
                const float4 x1 = *(const float4*)(pW + rr*SAW + 4);
                float A[8];
                #pragma unroll
                for (int l = 0; l < 8; l++) {
                    const float4 d0 = *(const float4*)&c_D[l*8];
                    const float4 d1 = *(const float4*)&c_D[l*8 + 4];
                    A[l] = fmaf(x1.w, d1.w, fmaf(x1.z, d1.z, fmaf(x1.y, d1.y,
                           fmaf(x1.x, d1.x, fmaf(x0.w, d0.w, fmaf(x0.z, d0.z,
                           fmaf(x0.y, d0.y, x0.x * d0.x)))))));
                }
                *(float4*)(pW + rr*SAW)     = make_float4(A[0], A[1], A[2], A[3]);
                *(float4*)(pW + rr*SAW + 4) = make_float4(A[4], A[5], A[6], A[7]);
            }
        } else {
            // chroma: A'' (4x8) = Xh * E^T, E[l][h] = D[l][2h]+D[l][2h+1]
            const float* pC = &s_c[c-1][by*4][bx*4];
            const float4 xh = *(const float4*)(pC + r*SCW);
            float A[8];
            #pragma unroll
            for (int l = 0; l < 8; l++) {
                const float4 d0 = *(const float4*)&c_D[l*8];
                const float4 d1 = *(const float4*)&c_D[l*8 + 4];
                float e0 = d0.x + d0.y, e1 = d0.z + d0.w;
                float e2 = d1.x + d1.y, e3 = d1.z + d1.w;
                A[l] = fmaf(xh.w, e3, fmaf(xh.z, e2, fmaf(xh.y, e1, xh.x * e0)));
            }
            *(float4*)(pW + r*SAW)     = make_float4(A[0], A[1], A[2], A[3]);
            *(float4*)(pW + r*SAW + 4) = make_float4(A[4], A[5], A[6], A[7]);
        }
    }
    __syncthreads();

    // ---- stage 2: F = D * A' (transpose), quant/dequant, V = dec * D ----
    float Va[8], Vb[8];
    if (act) {
        float Fa[8], Fb[8];
        #pragma unroll
        for (int l = 0; l < 8; l++) { Fa[l] = 0.0f; Fb[l] = 0.0f; }
        if (c == 0) {
            #pragma unroll
            for (int j = 0; j < 8; j++) {
                const float da = s_d[ra][j];
                const float db = s_d[rb][j];
                const float4 a0 = *(const float4*)(pW + j*SAW);
                const float4 a1 = *(const float4*)(pW + j*SAW + 4);
                Fa[0] = fmaf(da, a0.x, Fa[0]);  Fb[0] = fmaf(db, a0.x, Fb[0]);
                Fa[1] = fmaf(da, a0.y, Fa[1]);  Fb[1] = fmaf(db, a0.y, Fb[1]);
                Fa[2] = fmaf(da, a0.z, Fa[2]);  Fb[2] = fmaf(db, a0.z, Fb[2]);
                Fa[3] = fmaf(da, a0.w, Fa[3]);  Fb[3] = fmaf(db, a0.w, Fb[3]);
                Fa[4] = fmaf(da, a1.x, Fa[4]);  Fb[4] = fmaf(db, a1.x, Fb[4]);
                Fa[5] = fmaf(da, a1.y, Fa[5]);  Fb[5] = fmaf(db, a1.y, Fb[5]);
                Fa[6] = fmaf(da, a1.z, Fa[6]);  Fb[6] = fmaf(db, a1.z, Fb[6]);
                Fa[7] = fmaf(da, a1.w, Fa[7]);  Fb[7] = fmaf(db, a1.w, Fb[7]);
            }
        } else {
            #pragma unroll
            for (int m = 0; m < 4; m++) {
                const float ea = s_e[ra][m];
                const float eb = s_e[rb][m];
                const float4 a0 = *(const float4*)(pW + m*SAW);
                const float4 a1 = *(const float4*)(pW + m*SAW + 4);
                Fa[0] = fmaf(ea, a0.x, Fa[0]);  Fb[0] = fmaf(eb, a0.x, Fb[0]);
                Fa[1] = fmaf(ea, a0.y, Fa[1]);  Fb[1] = fmaf(eb, a0.y, Fb[1]);
                Fa[2] = fmaf(ea, a0.z, Fa[2]);  Fb[2] = fmaf(eb, a0.z, Fb[2]);
                Fa[3] = fmaf(ea, a0.w, Fa[3]);  Fb[3] = fmaf(eb, a0.w, Fb[3]);
                Fa[4] = fmaf(ea, a1.x, Fa[4]);  Fb[4] = fmaf(eb, a1.x, Fb[4]);
                Fa[5] = fmaf(ea, a1.y, Fa[5]);  Fb[5] = fmaf(eb, a1.y, Fb[5]);
                Fa[6] = fmaf(ea, a1.z, Fa[6]);  Fb[6] = fmaf(eb, a1.z, Fb[6]);
                Fa[7] = fmaf(ea, a1.w, Fa[7]);  Fb[7] = fmaf(eb, a1.w, Fb[7]);
            }
        }
        // quant / dequant (reciprocal)
        float deca[8], decb[8];
        {
            const float4 q0  = *(const float4*)&s_q[c][ra][0];
            const float4 q1  = *(const float4*)&s_q[c][ra][4];
            const float4 rq0 = *(const float4*)&s_rq[c][ra][0];
            const float4 rq1 = *(const float4*)&s_rq[c][ra][4];
            deca[0] = rintf(rintf(Fa[0]*rq0.x)*q0.x);  deca[1] = rintf(rintf(Fa[1]*rq0.y)*q0.y);
            deca[2] = rintf(rintf(Fa[2]*rq0.z)*q0.z);  deca[3] = rintf(rintf(Fa[3]*rq0.w)*q0.w);
            deca[4] = rintf(rintf(Fa[4]*rq1.x)*q1.x);  deca[5] = rintf(rintf(Fa[5]*rq1.y)*q1.y);
            deca[6] = rintf(rintf(Fa[6]*rq1.z)*q1.z);  deca[7] = rintf(rintf(Fa[7]*rq1.w)*q1.w);
        }
        {
            const float4 q0  = *(const float4*)&s_q[c][rb][0];
            const float4 q1  = *(const float4*)&s_q[c][rb][4];
            const float4 rq0 = *(const float4*)&s_rq[c][rb][0];
            const float4 rq1 = *(const float4*)&s_rq[c][rb][4];
            decb[0] = rintf(rintf(Fb[0]*rq0.x)*q0.x);  decb[1] = rintf(rintf(Fb[1]*rq0.y)*q0.y);
            decb[2] = rintf(rintf(Fb[2]*rq0.z)*q0.z);  decb[3] = rintf(rintf(Fb[3]*rq0.w)*q0.w);
            decb[4] = rintf(rintf(Fb[4]*rq1.x)*q1.x);  decb[5] = rintf(rintf(Fb[5]*rq1.y)*q1.y);
            decb[6] = rintf(rintf(Fb[6]*rq1.z)*q1.z);  decb[7] = rintf(rintf(Fb[7]*rq1.w)*q1.w);
        }
        // V = dec * D (row-local; uniform const coeffs)
        #pragma unroll
        for (int l = 0; l < 8; l++) { Va[l] = 0.0f; Vb[l] = 0.0f; }
        #pragma unroll
        for (int k = 0; k < 8; k++) {
            const float4 d0 = *(const float4*)&c_D[k*8];
            const float4 d1 = *(const float4*)&c_D[k*8 + 4];
            const float ta = deca[k], tb = decb[k];
            Va[0] = fmaf(ta, d0.x, Va[0]);  Vb[0] = fmaf(tb, d0.x, Vb[0]);
            Va[1] = fmaf(ta, d0.y, Va[1]);  Vb[1] = fmaf(tb, d0.y, Vb[1]);
            Va[2] = fmaf(ta, d0.z, Va[2]);  Vb[2] = fmaf(tb, d0.z, Vb[2]);
            Va[3] = fmaf(ta, d0.w, Va[3]);  Vb[3] = fmaf(tb, d0.w, Vb[3]);
            Va[4] = fmaf(ta, d1.x, Va[4]);  Vb[4] = fmaf(tb, d1.x, Vb[4]);
            Va[5] = fmaf(ta, d1.y, Va[5]);  Vb[5] = fmaf(tb, d1.y, Vb[5]);
            Va[6] = fmaf(ta, d1.z, Va[6]);  Vb[6] = fmaf(tb, d1.z, Vb[6]);
            Va[7] = fmaf(ta, d1.w, Va[7]);  Vb[7] = fmaf(tb, d1.w, Vb[7]);
        }
    }
    __syncthreads();  // all A' reads done -> safe to overwrite
    if (act) {
        *(float4*)(pW + ra*SAW)     = make_float4(Va[0], Va[1], Va[2], Va[3]);
        *(float4*)(pW + ra*SAW + 4) = make_float4(Va[4], Va[5], Va[6], Va[7]);
        *(float4*)(pW + rb*SAW)     = make_float4(Vb[0], Vb[1], Vb[2], Vb[3]);
        *(float4*)(pW + rb*SAW + 4) = make_float4(Vb[4], Vb[5], Vb[6], Vb[7]);
    }
    __syncthreads();

    // ---- stage 3: Z = D^T * V (transpose) ----
    float zA[8], zB[8];
    if (act) {
        #pragma unroll
        for (int l = 0; l < 8; l++) { zA[l] = 0.0f; zB[l] = 0.0f; }
        #pragma unroll
        for (int j = 0; j < 8; j++) {
            const float da = s_dt[ra][j];
            const float db = s_dt[rb][j];
            const float4 v0 = *(const float4*)(pW + j*SAW);
            const float4 v1 = *(const float4*)(pW + j*SAW + 4);
            zA[0] = fmaf(da, v0.x, zA[0]);  zB[0] = fmaf(db, v0.x, zB[0]);
            zA[1] = fmaf(da, v0.y, zA[1]);  zB[1] = fmaf(db, v0.y, zB[1]);
            zA[2] = fmaf(da, v0.z, zA[2]);  zB[2] = fmaf(db, v0.z, zB[2]);
            zA[3] = fmaf(da, v0.w, zA[3]);  zB[3] = fmaf(db, v0.w, zB[3]);
            zA[4] = fmaf(da, v1.x, zA[4]);  zB[4] = fmaf(db, v1.x, zB[4]);
            zA[5] = fmaf(da, v1.y, zA[5]);  zB[5] = fmaf(db, v1.y, zB[5]);
            zA[6] = fmaf(da, v1.z, zA[6]);  zB[6] = fmaf(db, v1.z, zB[6]);
            zA[7] = fmaf(da, v1.w, zA[7]);  zB[7] = fmaf(db, v1.w, zB[7]);
        }
        const float off = (c == 0) ? 128.0f : 0.0f;
        #pragma unroll
        for (int l = 0; l < 8; l++) { zA[l] += off; zB[l] += off; }
    }
    __syncthreads();  // all V reads done -> safe to overwrite
    if (act) {
        *(float4*)(pW + ra*SAW)     = make_float4(zA[0], zA[1], zA[2], zA[3]);
        *(float4*)(pW + ra*SAW + 4) = make_float4(zA[4], zA[5], zA[6], zA[7]);
        *(float4*)(pW + rb*SAW)     = make_float4(zB[0], zB[1], zB[2], zB[3]);
        *(float4*)(pW + rb*SAW + 4) = make_float4(zB[4], zB[5], zB[6], zB[7]);
    }
    __syncthreads();

    // ---- phase 5: YCbCr -> RGB, clip, round, store ----
    {
        const int py  = tid >> 4;
        const int px4 = (tid & 15) * 4;
        const float4 yv  = *(const float4*)&s_a[0][py][px4];
        const float4 cbv = *(const float4*)&s_a[1][py][px4];
        const float4 crv = *(const float4*)&s_a[2][py][px4];

        #define FIN(v) (rintf(fminf(fmaxf((v), 0.0f), 255.0f)) * (1.0f/255.0f))
        float4 R, G, Bv;
        R.x = FIN(fmaf(1.402f, crv.x, yv.x));  R.y = FIN(fmaf(1.402f, crv.y, yv.y));
        R.z = FIN(fmaf(1.402f, crv.z, yv.z));  R.w = FIN(fmaf(1.402f, crv.w, yv.w));
        G.x = FIN(fmaf(-0.714136286f, crv.x, fmaf(-0.344136286f, cbv.x, yv.x)));
        G.y = FIN(fmaf(-0.714136286f, crv.y, fmaf(-0.344136286f, cbv.y, yv.y)));
        G.z = FIN(fmaf(-0.714136286f, crv.z, fmaf(-0.344136286f, cbv.z, yv.z)));
        G.w = FIN(fmaf(-0.714136286f, crv.w, fmaf(-0.344136286f, cbv.w, yv.w)));
        Bv.x = FIN(fmaf(1.772f, cbv.x, yv.x)); Bv.y = FIN(fmaf(1.772f, cbv.y, yv.y));
        Bv.z = FIN(fmaf(1.772f, cbv.z, yv.z)); Bv.w = FIN(fmaf(1.772f, cbv.w, yv.w));

        const size_t idx = (size_t)(ty0 + py) * WIMG + (tx0 + px4);
        *(float4*)&obase[idx]           = R;
        *(float4*)&obase[plane + idx]   = G;
        *(float4*)&obase[2*plane + idx] = Bv;
    }
}

extern "C" void kernel_launch(void* const* d_in, const int* in_sizes, int n_in,
                              void* d_out, int out_size)
{
    const float* x = nullptr;
    const float* q = nullptr;
    const float* d = nullptr;
    int nimg = 0;
    for (int i = 0; i < n_in; i++) {
        if (in_sizes[i] == 192)      q = (const float*)d_in[i];
        else if (in_sizes[i] == 64)  d = (const float*)d_in[i];
        else { x = (const float*)d_in[i]; nimg = in_sizes[i] / (3 * HIMG * WIMG); }
    }
    cudaMemcpyToSymbolAsync(c_D, d, 64 * sizeof(float), 0,
                            cudaMemcpyDeviceToDevice, 0);
    dim3 grid(WIMG / TW, HIMG / TH, nimg);
    jpeg_kernel<<<grid, NT>>>(x, q, d, (float*)d_out);
}